// round 4
// baseline (speedup 1.0000x reference)
#include <cuda_runtime.h>
#include <cstdint>

#define NN   50000
#define FF   128
#define H1   4
#define C1   64
#define HC1  256     // H1*C1
#define C2   64
#define EE   400000
#define ETOT (EE + NN)

// ---------------- scratch (static __device__, no allocs) ----------------
__device__ __align__(16) float    g_xs1[(size_t)NN * HC1];   // x @ W1_src
__device__ __align__(16) float    g_h  [(size_t)NN * HC1];   // layer1 agg -> hidden
__device__ __align__(16) float    g_xs2[(size_t)NN * C2];    // h @ W2_src
__device__ __align__(16) float    g_as1[NN * H1];
__device__ __align__(16) float    g_ad1[NN * H1];
__device__ __align__(16) unsigned g_m1 [NN * H1];
__device__ __align__(16) float    g_den1[NN * H1];
__device__ __align__(16) float    g_as2[NN];
__device__ __align__(16) float    g_ad2[NN];
__device__ __align__(16) unsigned g_m2 [NN];
__device__ __align__(16) float    g_den2[NN];
__device__ __align__(16) float    g_ex1[(size_t)ETOT * H1];
__device__ __align__(16) float    g_ex2[ETOT];
__device__ __align__(16) float    g_v1dst[FF * H1];          // W1_dst folded with att1_dst
__device__ __align__(16) float    g_v2dst[HC1];              // W2_dst folded with att2_dst
__device__ __align__(16) int      g_src[ETOT];               // decoded edges (incl self loops)
__device__ __align__(16) int      g_dst[ETOT];
__device__ int g_is32;                                       // edge_index dtype flag

// ---------------- helpers ----------------
__device__ __forceinline__ unsigned fenc(float f) {
    unsigned u = __float_as_uint(f);
    return (u & 0x80000000u) ? ~u : (u | 0x80000000u);
}
__device__ __forceinline__ float fdec(unsigned u) {
    return __uint_as_float((u & 0x80000000u) ? (u & 0x7fffffffu) : ~u);
}
__device__ __forceinline__ float lrelu(float v) { return v > 0.f ? v : 0.2f * v; }

__device__ __forceinline__ void red_add_v4(float* p, float4 v) {
    asm volatile("red.global.add.v4.f32 [%0], {%1,%2,%3,%4};"
                 :: "l"(p), "f"(v.x), "f"(v.y), "f"(v.z), "f"(v.w) : "memory");
}

// ---------------- edge dtype detection + decode ----------------
// If edge_index is int64 (values < 2^32), every odd int32 word is 0.
// If it's int32, odd words are real node indices (~uniform [0,50000)) — not all zero.
__global__ void k_detect(const int* __restrict__ ei32) {
    int lane = threadIdx.x;            // 32 threads
    int nz = 0;
    #pragma unroll
    for (int j = 0; j < 4; j++) nz |= ei32[2 * (lane * 4 + j) + 1];
    unsigned anynz = __ballot_sync(0xffffffffu, nz != 0);
    if (lane == 0) g_is32 = (anynz != 0u) ? 1 : 0;
}

__global__ void k_decode(const void* __restrict__ ei) {
    int e = blockIdx.x * blockDim.x + threadIdx.x;
    if (e >= ETOT) return;
    int s, d;
    if (e < EE) {
        if (g_is32) {
            const int* p = (const int*)ei;
            s = p[e]; d = p[EE + e];
        } else {
            const long long* p = (const long long*)ei;
            s = (int)p[e]; d = (int)p[EE + e];
        }
    } else {
        s = e - EE; d = s;
    }
    g_src[e] = s; g_dst[e] = d;
}

// ---------------- fold W_dst with att_dst ----------------
__global__ void k_prep(const float* __restrict__ W1d, const float* __restrict__ a1d,
                       const float* __restrict__ W2d, const float* __restrict__ a2d) {
    int t = threadIdx.x;
    if (t < FF * H1) {
        int f = t >> 2, h = t & 3;
        float s = 0.f;
        #pragma unroll 8
        for (int c = 0; c < C1; c++) s += W1d[f * HC1 + h * C1 + c] * a1d[h * C1 + c];
        g_v1dst[f * H1 + h] = s;
    }
    if (t < HC1) {
        float s = 0.f;
        #pragma unroll 8
        for (int c = 0; c < C2; c++) s += W2d[t * C2 + c] * a2d[c];
        g_v2dst[t] = s;
    }
}

// ---------------- tiled fp32 GEMM: C[M,N] = A[M,K] @ B[K,N] ----------------
template <int BM, int BN, int BK, int TM, int TN>
__global__ void sgemm(const float* __restrict__ A, const float* __restrict__ B,
                      float* __restrict__ C, int M, int K, int N) {
    __shared__ float As[BK][BM];
    __shared__ float Bs[BK][BN];
    constexpr int THREADS = (BM / TM) * (BN / TN);
    const int t  = threadIdx.x;
    const int tx = t % (BN / TN);
    const int ty = t / (BN / TN);
    const int row0 = blockIdx.y * BM;
    const int col0 = blockIdx.x * BN;

    float acc[TM][TN];
    #pragma unroll
    for (int i = 0; i < TM; i++)
        #pragma unroll
        for (int j = 0; j < TN; j++) acc[i][j] = 0.f;

    constexpr int A_F4 = BM * BK / 4;
    constexpr int B_F4 = BK * BN / 4;

    for (int k0 = 0; k0 < K; k0 += BK) {
        #pragma unroll
        for (int i = t; i < A_F4; i += THREADS) {
            int r = i / (BK / 4), c4 = i % (BK / 4);
            float4 v = make_float4(0.f, 0.f, 0.f, 0.f);
            int gr = row0 + r;
            if (gr < M) v = *(const float4*)&A[(size_t)gr * K + k0 + c4 * 4];
            As[c4 * 4 + 0][r] = v.x; As[c4 * 4 + 1][r] = v.y;
            As[c4 * 4 + 2][r] = v.z; As[c4 * 4 + 3][r] = v.w;
        }
        #pragma unroll
        for (int i = t; i < B_F4; i += THREADS) {
            int r = i / (BN / 4), c4 = i % (BN / 4);
            *(float4*)&Bs[r][c4 * 4] = *(const float4*)&B[(size_t)(k0 + r) * N + col0 + c4 * 4];
        }
        __syncthreads();
        #pragma unroll
        for (int k = 0; k < BK; k++) {
            float a[TM], b[TN];
            #pragma unroll
            for (int i = 0; i < TM; i += 4) *(float4*)&a[i] = *(float4*)&As[k][ty * TM + i];
            #pragma unroll
            for (int j = 0; j < TN; j += 4) *(float4*)&b[j] = *(float4*)&Bs[k][tx * TN + j];
            #pragma unroll
            for (int i = 0; i < TM; i++)
                #pragma unroll
                for (int j = 0; j < TN; j++) acc[i][j] += a[i] * b[j];
        }
        __syncthreads();
    }
    #pragma unroll
    for (int i = 0; i < TM; i++) {
        int gr = row0 + ty * TM + i;
        if (gr < M) {
            #pragma unroll
            for (int j = 0; j < TN; j += 4)
                *(float4*)&C[(size_t)gr * N + col0 + tx * TN + j] =
                    make_float4(acc[i][j], acc[i][j + 1], acc[i][j + 2], acc[i][j + 3]);
        }
    }
}

// ---------------- layer-1 per-node attention scalars (warp/node) ----------------
__global__ void k_scores1(const float* __restrict__ x, const float* __restrict__ att_src) {
    int warp = (blockIdx.x * blockDim.x + threadIdx.x) >> 5;
    int lane = threadIdx.x & 31;
    if (warp >= NN) return;

    // a_s[n,h] = sum_c xs1[n,h*64+c]*att_src[h*64+c]
    const float* row = g_xs1 + (size_t)warp * HC1;
    int base = lane * 8;
    float s = 0.f;
    #pragma unroll
    for (int j = 0; j < 8; j++) s += row[base + j] * att_src[base + j];
    s += __shfl_down_sync(0xffffffffu, s, 4);
    s += __shfl_down_sync(0xffffffffu, s, 2);
    s += __shfl_down_sync(0xffffffffu, s, 1);
    if ((lane & 7) == 0) g_as1[warp * H1 + (lane >> 3)] = s;

    // a_d[n,h] = sum_f x[n,f]*v1dst[f,h]
    float acc0 = 0.f, acc1 = 0.f, acc2 = 0.f, acc3 = 0.f;
    const float* xr = x + (size_t)warp * FF;
    #pragma unroll
    for (int f = lane; f < FF; f += 32) {
        float xv = xr[f];
        float4 v = *(const float4*)&g_v1dst[f * H1];
        acc0 += xv * v.x; acc1 += xv * v.y; acc2 += xv * v.z; acc3 += xv * v.w;
    }
    #pragma unroll
    for (int o = 16; o > 0; o >>= 1) {
        acc0 += __shfl_down_sync(0xffffffffu, acc0, o);
        acc1 += __shfl_down_sync(0xffffffffu, acc1, o);
        acc2 += __shfl_down_sync(0xffffffffu, acc2, o);
        acc3 += __shfl_down_sync(0xffffffffu, acc3, o);
    }
    if (lane == 0) *(float4*)&g_ad1[warp * H1] = make_float4(acc0, acc1, acc2, acc3);
}

// ---------------- layer-1 edge passes ----------------
__global__ void k_edge_max1() {
    int e = blockIdx.x * blockDim.x + threadIdx.x;
    if (e >= ETOT) return;
    int s = g_src[e], d = g_dst[e];
    float4 as = *(const float4*)&g_as1[s * H1];
    float4 ad = *(const float4*)&g_ad1[d * H1];
    atomicMax(&g_m1[d * H1 + 0], fenc(lrelu(as.x + ad.x)));
    atomicMax(&g_m1[d * H1 + 1], fenc(lrelu(as.y + ad.y)));
    atomicMax(&g_m1[d * H1 + 2], fenc(lrelu(as.z + ad.z)));
    atomicMax(&g_m1[d * H1 + 3], fenc(lrelu(as.w + ad.w)));
}

__global__ void k_edge_exp1() {
    int e = blockIdx.x * blockDim.x + threadIdx.x;
    if (e >= ETOT) return;
    int s = g_src[e], d = g_dst[e];
    float4 as = *(const float4*)&g_as1[s * H1];
    float4 ad = *(const float4*)&g_ad1[d * H1];
    float4 ex;
    ex.x = __expf(lrelu(as.x + ad.x) - fdec(g_m1[d * H1 + 0]));
    ex.y = __expf(lrelu(as.y + ad.y) - fdec(g_m1[d * H1 + 1]));
    ex.z = __expf(lrelu(as.z + ad.z) - fdec(g_m1[d * H1 + 2]));
    ex.w = __expf(lrelu(as.w + ad.w) - fdec(g_m1[d * H1 + 3]));
    *(float4*)&g_ex1[(size_t)e * H1] = ex;
    red_add_v4(&g_den1[d * H1], ex);
}

__global__ void k_edge_agg1() {
    int warp = (blockIdx.x * blockDim.x + threadIdx.x) >> 5;
    int lane = threadIdx.x & 31;
    if (warp >= ETOT) return;
    int s = g_src[warp], d = g_dst[warp];
    float4 ex  = *(const float4*)&g_ex1[(size_t)warp * H1];
    float4 den = *(const float4*)&g_den1[d * H1];
    float alpha[H1] = { ex.x / den.x, ex.y / den.y, ex.z / den.z, ex.w / den.w };
    const float4* srow = (const float4*)&g_xs1[(size_t)s * HC1];
    float*        drow = &g_h[(size_t)d * HC1];
    #pragma unroll
    for (int it = 0; it < 2; it++) {
        int i = lane + it * 32;           // float4 index 0..63
        float a = alpha[i >> 4];          // 16 float4 per head
        float4 v = srow[i];
        red_add_v4(drow + i * 4, make_float4(v.x * a, v.y * a, v.z * a, v.w * a));
    }
}

__global__ void k_bias_relu1(const float* __restrict__ b1) {
    int i = blockIdx.x * blockDim.x + threadIdx.x;     // float4 index
    if (i >= NN * HC1 / 4) return;
    float4 v = ((float4*)g_h)[i];
    float4 b = *(const float4*)&b1[(i & (HC1 / 4 - 1)) * 4];
    v.x = fmaxf(v.x + b.x, 0.f); v.y = fmaxf(v.y + b.y, 0.f);
    v.z = fmaxf(v.z + b.z, 0.f); v.w = fmaxf(v.w + b.w, 0.f);
    ((float4*)g_h)[i] = v;
}

// ---------------- layer-2 per-node attention scalars ----------------
__global__ void k_scores2(const float* __restrict__ att2_src) {
    int warp = (blockIdx.x * blockDim.x + threadIdx.x) >> 5;
    int lane = threadIdx.x & 31;
    if (warp >= NN) return;

    const float* row = g_xs2 + (size_t)warp * C2;
    float s = row[lane] * att2_src[lane] + row[lane + 32] * att2_src[lane + 32];

    float t = 0.f;
    const float* hr = g_h + (size_t)warp * HC1;
    #pragma unroll
    for (int f = lane; f < HC1; f += 32) t += hr[f] * g_v2dst[f];

    #pragma unroll
    for (int o = 16; o > 0; o >>= 1) {
        s += __shfl_down_sync(0xffffffffu, s, o);
        t += __shfl_down_sync(0xffffffffu, t, o);
    }
    if (lane == 0) { g_as2[warp] = s; g_ad2[warp] = t; }
}

// ---------------- layer-2 edge passes ----------------
__global__ void k_edge_max2() {
    int e = blockIdx.x * blockDim.x + threadIdx.x;
    if (e >= ETOT) return;
    int s = g_src[e], d = g_dst[e];
    atomicMax(&g_m2[d], fenc(lrelu(g_as2[s] + g_ad2[d])));
}

__global__ void k_edge_exp2() {
    int e = blockIdx.x * blockDim.x + threadIdx.x;
    if (e >= ETOT) return;
    int s = g_src[e], d = g_dst[e];
    float ex = __expf(lrelu(g_as2[s] + g_ad2[d]) - fdec(g_m2[d]));
    g_ex2[e] = ex;
    atomicAdd(&g_den2[d], ex);
}

__global__ void k_edge_agg2(float* __restrict__ out) {
    int g = blockIdx.x * blockDim.x + threadIdx.x;
    int e = g >> 4, c = g & 15;                 // 16 threads (float4 chunks) per edge
    if (e >= ETOT) return;
    int s = g_src[e], d = g_dst[e];
    float alpha = g_ex2[e] / g_den2[d];
    float4 v = ((const float4*)&g_xs2[(size_t)s * C2])[c];
    red_add_v4(out + (size_t)d * C2 + c * 4,
               make_float4(v.x * alpha, v.y * alpha, v.z * alpha, v.w * alpha));
}

__global__ void k_bias2(float* __restrict__ out, const float* __restrict__ b2) {
    int i = blockIdx.x * blockDim.x + threadIdx.x;     // float4 index
    if (i >= NN * C2 / 4) return;
    float4 v = ((float4*)out)[i];
    float4 b = *(const float4*)&b2[(i & (C2 / 4 - 1)) * 4];
    v.x += b.x; v.y += b.y; v.z += b.z; v.w += b.w;
    ((float4*)out)[i] = v;
}

// ---------------- launcher ----------------
extern "C" void kernel_launch(void* const* d_in, const int* in_sizes, int n_in,
                              void* d_out, int out_size) {
    const float* x    = (const float*)d_in[0];
    const void*  ei   = d_in[1];                 // int32 or int64, detected at runtime
    const float* W1s  = (const float*)d_in[2];
    const float* W1d  = (const float*)d_in[3];
    const float* a1s  = (const float*)d_in[4];
    const float* a1d  = (const float*)d_in[5];
    const float* b1   = (const float*)d_in[6];
    const float* W2s  = (const float*)d_in[7];
    const float* W2d  = (const float*)d_in[8];
    const float* a2s  = (const float*)d_in[9];
    const float* a2d  = (const float*)d_in[10];
    const float* b2   = (const float*)d_in[11];
    float* out = (float*)d_out;

    cudaStream_t st = 0;

    // zero accumulators / softmax state
    void *p_h, *p_m1, *p_d1, *p_m2, *p_d2;
    cudaGetSymbolAddress(&p_h,  g_h);
    cudaGetSymbolAddress(&p_m1, g_m1);
    cudaGetSymbolAddress(&p_d1, g_den1);
    cudaGetSymbolAddress(&p_m2, g_m2);
    cudaGetSymbolAddress(&p_d2, g_den2);
    cudaMemsetAsync(p_h,  0, (size_t)NN * HC1 * 4, st);
    cudaMemsetAsync(p_m1, 0, (size_t)NN * H1 * 4, st);
    cudaMemsetAsync(p_d1, 0, (size_t)NN * H1 * 4, st);
    cudaMemsetAsync(p_m2, 0, (size_t)NN * 4, st);
    cudaMemsetAsync(p_d2, 0, (size_t)NN * 4, st);
    cudaMemsetAsync(out,  0, (size_t)NN * C2 * 4, st);

    k_detect<<<1, 32, 0, st>>>((const int*)ei);
    int eb = (ETOT + 255) / 256;
    k_decode<<<eb, 256, 0, st>>>(ei);

    k_prep<<<1, 512, 0, st>>>(W1d, a1d, W2d, a2d);

    // xs1 = x @ W1_src   [50000,128] x [128,256]
    {
        float* xs1; cudaGetSymbolAddress((void**)&xs1, g_xs1);
        dim3 grid(HC1 / 64, (NN + 127) / 128);
        sgemm<128, 64, 16, 8, 4><<<grid, 256, 0, st>>>(x, W1s, xs1, NN, FF, HC1);
    }

    k_scores1<<<(NN * 32 + 255) / 256, 256, 0, st>>>(x, a1s);

    k_edge_max1<<<eb, 256, 0, st>>>();
    k_edge_exp1<<<eb, 256, 0, st>>>();
    k_edge_agg1<<<(ETOT * 32 + 255) / 256, 256, 0, st>>>();
    k_bias_relu1<<<(NN * HC1 / 4 + 255) / 256, 256, 0, st>>>(b1);

    // xs2 = h @ W2_src   [50000,256] x [256,64]
    {
        float *h, *xs2;
        cudaGetSymbolAddress((void**)&h, g_h);
        cudaGetSymbolAddress((void**)&xs2, g_xs2);
        dim3 grid(C2 / 64, (NN + 127) / 128);
        sgemm<128, 64, 16, 8, 4><<<grid, 256, 0, st>>>(h, W2s, xs2, NN, HC1, C2);
    }

    k_scores2<<<(NN * 32 + 255) / 256, 256, 0, st>>>(a2s);
    k_edge_max2<<<eb, 256, 0, st>>>();
    k_edge_exp2<<<eb, 256, 0, st>>>();
    k_edge_agg2<<<(ETOT * 16 + 255) / 256, 256, 0, st>>>(out);
    k_bias2<<<(NN * C2 / 4 + 255) / 256, 256, 0, st>>>(out, b2);
}

// round 5
// speedup vs baseline: 1.0993x; 1.0993x over previous
#include <cuda_runtime.h>
#include <cstdint>
#include <cfloat>

#define NN   50000
#define FF   128
#define H1   4
#define C1   64
#define HC1  256     // H1*C1
#define C2   64
#define EE   400000
#define ETOT (EE + NN)

// ---------------- scratch (static __device__, no allocs) ----------------
__device__ __align__(16) float g_xs1[(size_t)NN * HC1];   // x @ W1_src
__device__ __align__(16) float g_h  [(size_t)NN * HC1];   // hidden (post bias+relu)
__device__ __align__(16) float g_xs2[(size_t)NN * C2];    // h @ W2_src
__device__ __align__(16) float g_as1[NN * H1];
__device__ __align__(16) float g_ad1[NN * H1];
__device__ __align__(16) float g_as2[NN];
__device__ __align__(16) float g_ad2[NN];
__device__ __align__(16) float g_v1src[FF * H1];          // W1_src folded with att1_src
__device__ __align__(16) float g_v1dst[FF * H1];          // W1_dst folded with att1_dst
__device__ __align__(16) float g_v2src[HC1];
__device__ __align__(16) float g_v2dst[HC1];
__device__ __align__(16) int   g_src[ETOT];
__device__ __align__(16) int   g_dst[ETOT];
__device__ __align__(16) int   g_deg[NN];
__device__ __align__(16) int   g_cnt[NN];
__device__ __align__(16) int   g_off[NN + 1];
__device__ __align__(16) int   g_csr[ETOT];               // src node per CSR slot
__device__ int g_is32;

// ---------------- helpers ----------------
__device__ __forceinline__ float lrelu(float v) { return v > 0.f ? v : 0.2f * v; }

// ---------------- edge dtype detection ----------------
__global__ void k_detect(const int* __restrict__ ei32) {
    int lane = threadIdx.x;            // 32 threads
    int nz = 0;
    #pragma unroll
    for (int j = 0; j < 4; j++) nz |= ei32[2 * (lane * 4 + j) + 1];
    unsigned anynz = __ballot_sync(0xffffffffu, nz != 0);
    if (lane == 0) g_is32 = (anynz != 0u) ? 1 : 0;
}

// decode edges (+self loops) and histogram destination degrees
__global__ void k_decode(const void* __restrict__ ei) {
    int e = blockIdx.x * blockDim.x + threadIdx.x;
    if (e >= ETOT) return;
    int s, d;
    if (e < EE) {
        if (g_is32) {
            const int* p = (const int*)ei;
            s = p[e]; d = p[EE + e];
        } else {
            const long long* p = (const long long*)ei;
            s = (int)p[e]; d = (int)p[EE + e];
        }
    } else {
        s = e - EE; d = s;
    }
    g_src[e] = s; g_dst[e] = d;
    atomicAdd(&g_deg[d], 1);
}

// single-block exclusive scan of g_deg -> g_off
__global__ void k_scan() {
    __shared__ int wsum[32];
    const int T = 1024;
    const int CH = (NN + T - 1) / T;     // 49
    int t = threadIdx.x;
    int lane = t & 31, w = t >> 5;
    int base = t * CH;
    int sum = 0;
    for (int i = 0; i < CH; i++) { int idx = base + i; if (idx < NN) sum += g_deg[idx]; }
    int v = sum;
    #pragma unroll
    for (int o = 1; o < 32; o <<= 1) {
        int u = __shfl_up_sync(0xffffffffu, v, o);
        if (lane >= o) v += u;
    }
    if (lane == 31) wsum[w] = v;
    __syncthreads();
    if (w == 0) {
        int u = wsum[lane];
        #pragma unroll
        for (int o = 1; o < 32; o <<= 1) {
            int q = __shfl_up_sync(0xffffffffu, u, o);
            if (lane >= o) u += q;
        }
        wsum[lane] = u;
    }
    __syncthreads();
    int ex = v - sum + (w ? wsum[w - 1] : 0);
    for (int i = 0; i < CH; i++) {
        int idx = base + i;
        if (idx < NN) { g_off[idx] = ex; ex += g_deg[idx]; }
    }
    if (t == 0) g_off[NN] = ETOT;
}

__global__ void k_fill() {
    int e = blockIdx.x * blockDim.x + threadIdx.x;
    if (e >= ETOT) return;
    int d = g_dst[e];
    int pos = g_off[d] + atomicAdd(&g_cnt[d], 1);
    g_csr[pos] = g_src[e];
}

// ---------------- fold att vectors into W matrices ----------------
__global__ void k_prep(const float* __restrict__ W1s, const float* __restrict__ a1s,
                       const float* __restrict__ W1d, const float* __restrict__ a1d,
                       const float* __restrict__ W2s, const float* __restrict__ a2s,
                       const float* __restrict__ W2d, const float* __restrict__ a2d) {
    int t = threadIdx.x;   // 512
    {
        int f = t >> 2, h = t & 3;
        float ss = 0.f, sd = 0.f;
        #pragma unroll 8
        for (int c = 0; c < C1; c++) {
            float av_s = a1s[h * C1 + c], av_d = a1d[h * C1 + c];
            ss += W1s[f * HC1 + h * C1 + c] * av_s;
            sd += W1d[f * HC1 + h * C1 + c] * av_d;
        }
        g_v1src[f * H1 + h] = ss;
        g_v1dst[f * H1 + h] = sd;
    }
    if (t < HC1) {
        float ss = 0.f, sd = 0.f;
        #pragma unroll 8
        for (int c = 0; c < C2; c++) {
            ss += W2s[t * C2 + c] * a2s[c];
            sd += W2d[t * C2 + c] * a2d[c];
        }
        g_v2src[t] = ss;
        g_v2dst[t] = sd;
    }
}

// ---------------- tiled fp32 GEMM: C[M,N] = A[M,K] @ B[K,N] ----------------
template <int BM, int BN, int BK, int TM, int TN>
__global__ void sgemm(const float* __restrict__ A, const float* __restrict__ B,
                      float* __restrict__ C, int M, int K, int N) {
    __shared__ float As[BK][BM];
    __shared__ float Bs[BK][BN];
    constexpr int THREADS = (BM / TM) * (BN / TN);
    const int t  = threadIdx.x;
    const int tx = t % (BN / TN);
    const int ty = t / (BN / TN);
    const int row0 = blockIdx.y * BM;
    const int col0 = blockIdx.x * BN;

    float acc[TM][TN];
    #pragma unroll
    for (int i = 0; i < TM; i++)
        #pragma unroll
        for (int j = 0; j < TN; j++) acc[i][j] = 0.f;

    constexpr int A_F4 = BM * BK / 4;
    constexpr int B_F4 = BK * BN / 4;

    for (int k0 = 0; k0 < K; k0 += BK) {
        #pragma unroll
        for (int i = t; i < A_F4; i += THREADS) {
            int r = i / (BK / 4), c4 = i % (BK / 4);
            float4 v = make_float4(0.f, 0.f, 0.f, 0.f);
            int gr = row0 + r;
            if (gr < M) v = *(const float4*)&A[(size_t)gr * K + k0 + c4 * 4];
            As[c4 * 4 + 0][r] = v.x; As[c4 * 4 + 1][r] = v.y;
            As[c4 * 4 + 2][r] = v.z; As[c4 * 4 + 3][r] = v.w;
        }
        #pragma unroll
        for (int i = t; i < B_F4; i += THREADS) {
            int r = i / (BN / 4), c4 = i % (BN / 4);
            *(float4*)&Bs[r][c4 * 4] = *(const float4*)&B[(size_t)(k0 + r) * N + col0 + c4 * 4];
        }
        __syncthreads();
        #pragma unroll
        for (int k = 0; k < BK; k++) {
            float a[TM], b[TN];
            #pragma unroll
            for (int i = 0; i < TM; i += 4) *(float4*)&a[i] = *(float4*)&As[k][ty * TM + i];
            #pragma unroll
            for (int j = 0; j < TN; j += 4) *(float4*)&b[j] = *(float4*)&Bs[k][tx * TN + j];
            #pragma unroll
            for (int i = 0; i < TM; i++)
                #pragma unroll
                for (int j = 0; j < TN; j++) acc[i][j] += a[i] * b[j];
        }
        __syncthreads();
    }
    #pragma unroll
    for (int i = 0; i < TM; i++) {
        int gr = row0 + ty * TM + i;
        if (gr < M) {
            #pragma unroll
            for (int j = 0; j < TN; j += 4)
                *(float4*)&C[(size_t)gr * N + col0 + tx * TN + j] =
                    make_float4(acc[i][j], acc[i][j + 1], acc[i][j + 2], acc[i][j + 3]);
        }
    }
}

// ---------------- layer-1 per-node attention scalars from x only ----------------
__global__ void k_scores1(const float* __restrict__ x) {
    int warp = (blockIdx.x * blockDim.x + threadIdx.x) >> 5;
    int lane = threadIdx.x & 31;
    if (warp >= NN) return;

    float4 xv = *(const float4*)&x[(size_t)warp * FF + lane * 4];
    float s0 = 0, s1 = 0, s2 = 0, s3 = 0, d0 = 0, d1 = 0, d2 = 0, d3 = 0;
    #pragma unroll
    for (int j = 0; j < 4; j++) {
        int f = lane * 4 + j;
        float xf = (j == 0) ? xv.x : (j == 1) ? xv.y : (j == 2) ? xv.z : xv.w;
        float4 vs = *(const float4*)&g_v1src[f * H1];
        float4 vd = *(const float4*)&g_v1dst[f * H1];
        s0 += xf * vs.x; s1 += xf * vs.y; s2 += xf * vs.z; s3 += xf * vs.w;
        d0 += xf * vd.x; d1 += xf * vd.y; d2 += xf * vd.z; d3 += xf * vd.w;
    }
    #pragma unroll
    for (int o = 16; o > 0; o >>= 1) {
        s0 += __shfl_xor_sync(0xffffffffu, s0, o);
        s1 += __shfl_xor_sync(0xffffffffu, s1, o);
        s2 += __shfl_xor_sync(0xffffffffu, s2, o);
        s3 += __shfl_xor_sync(0xffffffffu, s3, o);
        d0 += __shfl_xor_sync(0xffffffffu, d0, o);
        d1 += __shfl_xor_sync(0xffffffffu, d1, o);
        d2 += __shfl_xor_sync(0xffffffffu, d2, o);
        d3 += __shfl_xor_sync(0xffffffffu, d3, o);
    }
    if (lane == 0) {
        *(float4*)&g_as1[warp * H1] = make_float4(s0, s1, s2, s3);
        *(float4*)&g_ad1[warp * H1] = make_float4(d0, d1, d2, d3);
    }
}

// ---------------- fused layer-1: softmax + aggregate + bias/relu + layer-2 scores ----------------
__global__ void k_fused1(const float* __restrict__ b1) {
    int node = (blockIdx.x * blockDim.x + threadIdx.x) >> 5;
    int lane = threadIdx.x & 31;
    if (node >= NN) return;
    int beg = g_off[node], end = g_off[node + 1];

    float4 ad = *(const float4*)&g_ad1[node * H1];

    // pass 1: per-head max, edges distributed across lanes
    float4 mx = make_float4(-FLT_MAX, -FLT_MAX, -FLT_MAX, -FLT_MAX);
    for (int i = beg + lane; i < end; i += 32) {
        int s = g_csr[i];
        float4 as = *(const float4*)&g_as1[s * H1];
        mx.x = fmaxf(mx.x, lrelu(as.x + ad.x));
        mx.y = fmaxf(mx.y, lrelu(as.y + ad.y));
        mx.z = fmaxf(mx.z, lrelu(as.z + ad.z));
        mx.w = fmaxf(mx.w, lrelu(as.w + ad.w));
    }
    #pragma unroll
    for (int o = 16; o > 0; o >>= 1) {
        mx.x = fmaxf(mx.x, __shfl_xor_sync(0xffffffffu, mx.x, o));
        mx.y = fmaxf(mx.y, __shfl_xor_sync(0xffffffffu, mx.y, o));
        mx.z = fmaxf(mx.z, __shfl_xor_sync(0xffffffffu, mx.z, o));
        mx.w = fmaxf(mx.w, __shfl_xor_sync(0xffffffffu, mx.w, o));
    }

    // pass 2: lane owns 8 contiguous columns (head = lane/8); warp walks edges together
    int head = lane >> 3;
    int col0 = lane * 8;
    float mh  = (head == 0) ? mx.x : (head == 1) ? mx.y : (head == 2) ? mx.z : mx.w;
    float adh = (head == 0) ? ad.x : (head == 1) ? ad.y : (head == 2) ? ad.z : ad.w;
    float den = 0.f;
    float acc[8];
    #pragma unroll
    for (int j = 0; j < 8; j++) acc[j] = 0.f;

    #pragma unroll 2
    for (int i = beg; i < end; i++) {
        int s = g_csr[i];                                    // uniform across warp
        float ex = __expf(lrelu(g_as1[s * H1 + head] + adh) - mh);
        den += ex;
        const float4* r = (const float4*)&g_xs1[(size_t)s * HC1 + col0];
        float4 v0 = r[0], v1 = r[1];
        acc[0] += ex * v0.x; acc[1] += ex * v0.y; acc[2] += ex * v0.z; acc[3] += ex * v0.w;
        acc[4] += ex * v1.x; acc[5] += ex * v1.y; acc[6] += ex * v1.z; acc[7] += ex * v1.w;
    }
    float inv = 1.f / den;
    float hrow[8];
    #pragma unroll
    for (int j = 0; j < 8; j++) hrow[j] = fmaxf(acc[j] * inv + b1[col0 + j], 0.f);

    float* hp = &g_h[(size_t)node * HC1 + col0];
    *(float4*)&hp[0] = make_float4(hrow[0], hrow[1], hrow[2], hrow[3]);
    *(float4*)&hp[4] = make_float4(hrow[4], hrow[5], hrow[6], hrow[7]);

    // fused layer-2 scores: as2[n] = h·v2src, ad2[n] = h·v2dst
    float ps = 0.f, pd = 0.f;
    #pragma unroll
    for (int j = 0; j < 8; j++) {
        ps += hrow[j] * g_v2src[col0 + j];
        pd += hrow[j] * g_v2dst[col0 + j];
    }
    #pragma unroll
    for (int o = 16; o > 0; o >>= 1) {
        ps += __shfl_xor_sync(0xffffffffu, ps, o);
        pd += __shfl_xor_sync(0xffffffffu, pd, o);
    }
    if (lane == 0) { g_as2[node] = ps; g_ad2[node] = pd; }
}

// ---------------- fused layer-2: softmax + aggregate + bias ----------------
__global__ void k_fused2(float* __restrict__ out, const float* __restrict__ b2) {
    int node = (blockIdx.x * blockDim.x + threadIdx.x) >> 5;
    int lane = threadIdx.x & 31;
    if (node >= NN) return;
    int beg = g_off[node], end = g_off[node + 1];
    float adn = g_ad2[node];

    float mx = -FLT_MAX;
    for (int i = beg + lane; i < end; i += 32)
        mx = fmaxf(mx, lrelu(g_as2[g_csr[i]] + adn));
    #pragma unroll
    for (int o = 16; o > 0; o >>= 1)
        mx = fmaxf(mx, __shfl_xor_sync(0xffffffffu, mx, o));

    int col = lane * 2;
    float den = 0.f, a0 = 0.f, a1 = 0.f;
    #pragma unroll 2
    for (int i = beg; i < end; i++) {
        int s = g_csr[i];
        float ex = __expf(lrelu(g_as2[s] + adn) - mx);
        den += ex;
        float2 v = *(const float2*)&g_xs2[(size_t)s * C2 + col];
        a0 += ex * v.x; a1 += ex * v.y;
    }
    float inv = 1.f / den;
    *(float2*)&out[(size_t)node * C2 + col] =
        make_float2(a0 * inv + b2[col], a1 * inv + b2[col + 1]);
}

// ---------------- launcher ----------------
extern "C" void kernel_launch(void* const* d_in, const int* in_sizes, int n_in,
                              void* d_out, int out_size) {
    const float* x    = (const float*)d_in[0];
    const void*  ei   = d_in[1];
    const float* W1s  = (const float*)d_in[2];
    const float* W1d  = (const float*)d_in[3];
    const float* a1s  = (const float*)d_in[4];
    const float* a1d  = (const float*)d_in[5];
    const float* b1   = (const float*)d_in[6];
    const float* W2s  = (const float*)d_in[7];
    const float* W2d  = (const float*)d_in[8];
    const float* a2s  = (const float*)d_in[9];
    const float* a2d  = (const float*)d_in[10];
    const float* b2   = (const float*)d_in[11];
    float* out = (float*)d_out;

    cudaStream_t st = 0;

    void *p_deg, *p_cnt;
    cudaGetSymbolAddress(&p_deg, g_deg);
    cudaGetSymbolAddress(&p_cnt, g_cnt);
    cudaMemsetAsync(p_deg, 0, NN * sizeof(int), st);
    cudaMemsetAsync(p_cnt, 0, NN * sizeof(int), st);

    int eb = (ETOT + 255) / 256;
    k_detect<<<1, 32, 0, st>>>((const int*)ei);
    k_decode<<<eb, 256, 0, st>>>(ei);
    k_scan<<<1, 1024, 0, st>>>();
    k_fill<<<eb, 256, 0, st>>>();

    k_prep<<<1, 512, 0, st>>>(W1s, a1s, W1d, a1d, W2s, a2s, W2d, a2d);
    k_scores1<<<(NN * 32 + 255) / 256, 256, 0, st>>>(x);

    // xs1 = x @ W1_src   [50000,128] x [128,256]
    {
        float* xs1; cudaGetSymbolAddress((void**)&xs1, g_xs1);
        dim3 grid(HC1 / 64, (NN + 127) / 128);
        sgemm<128, 64, 16, 8, 4><<<grid, 256, 0, st>>>(x, W1s, xs1, NN, FF, HC1);
    }

    int nb = (NN * 32 + 255) / 256;
    k_fused1<<<nb, 256, 0, st>>>(b1);

    // xs2 = h @ W2_src   [50000,256] x [256,64]
    {
        float *h, *xs2;
        cudaGetSymbolAddress((void**)&h, g_h);
        cudaGetSymbolAddress((void**)&xs2, g_xs2);
        dim3 grid(C2 / 64, (NN + 127) / 128);
        sgemm<128, 64, 16, 8, 4><<<grid, 256, 0, st>>>(h, W2s, xs2, NN, HC1, C2);
    }

    k_fused2<<<nb, 256, 0, st>>>(out, b2);
}

// round 7
// speedup vs baseline: 1.1189x; 1.0178x over previous
#include <cuda_runtime.h>
#include <cstdint>
#include <cfloat>

#define NN   50000
#define FF   128
#define H1   4
#define C1   64
#define HC1  256     // H1*C1
#define C2   64
#define EE   400000
#define ETOT (EE + NN)

// ---------------- scratch (static __device__, no allocs) ----------------
__device__ __align__(16) float g_xs1[(size_t)NN * HC1];   // x @ W1_src
__device__ __align__(16) float g_h  [(size_t)NN * HC1];   // hidden (post bias+relu)
__device__ __align__(16) float g_xs2[(size_t)NN * C2];    // h @ W2_src
__device__ __align__(16) float g_as1[NN * H1];
__device__ __align__(16) float g_ad1[NN * H1];
__device__ __align__(16) float g_as2[NN];
__device__ __align__(16) float g_ad2[NN];
__device__ __align__(16) float g_v1src[FF * H1];
__device__ __align__(16) float g_v1dst[FF * H1];
__device__ __align__(16) float g_v2src[HC1];
__device__ __align__(16) float g_v2dst[HC1];
__device__ __align__(16) int   g_src[ETOT];
__device__ __align__(16) int   g_dst[ETOT];
__device__ __align__(16) int   g_deg[NN];
__device__ __align__(16) int   g_cnt[NN];
__device__ __align__(16) int   g_off[NN + 1];
__device__ __align__(16) int   g_csr[ETOT];
__device__ int g_is32;

// ---------------- helpers ----------------
__device__ __forceinline__ float lrelu(float v) { return v > 0.f ? v : 0.2f * v; }

__device__ __forceinline__ unsigned long long pack2(float lo, float hi) {
    unsigned long long r;
    asm("mov.b64 %0, {%1, %2};" : "=l"(r) : "r"(__float_as_uint(lo)), "r"(__float_as_uint(hi)));
    return r;
}
__device__ __forceinline__ void unpack2(unsigned long long v, float& lo, float& hi) {
    unsigned a, b;
    asm("mov.b64 {%0, %1}, %2;" : "=r"(a), "=r"(b) : "l"(v));
    lo = __uint_as_float(a); hi = __uint_as_float(b);
}
__device__ __forceinline__ void ffma2(unsigned long long& d, unsigned long long a, unsigned long long b) {
    asm("fma.rn.f32x2 %0, %1, %2, %3;" : "=l"(d) : "l"(a), "l"(b), "l"(d));
}

// ---------------- edge dtype detection ----------------
__global__ void k_detect(const int* __restrict__ ei32) {
    int lane = threadIdx.x;
    int nz = 0;
    #pragma unroll
    for (int j = 0; j < 4; j++) nz |= ei32[2 * (lane * 4 + j) + 1];
    unsigned anynz = __ballot_sync(0xffffffffu, nz != 0);
    if (lane == 0) g_is32 = (anynz != 0u) ? 1 : 0;
}

__global__ void k_decode(const void* __restrict__ ei) {
    int e = blockIdx.x * blockDim.x + threadIdx.x;
    if (e >= ETOT) return;
    int s, d;
    if (e < EE) {
        if (g_is32) {
            const int* p = (const int*)ei;
            s = p[e]; d = p[EE + e];
        } else {
            const long long* p = (const long long*)ei;
            s = (int)p[e]; d = (int)p[EE + e];
        }
    } else {
        s = e - EE; d = s;
    }
    g_src[e] = s; g_dst[e] = d;
    atomicAdd(&g_deg[d], 1);
}

// single-block exclusive scan of g_deg -> g_off
__global__ void k_scan() {
    __shared__ int wsum[32];
    const int T = 1024;
    const int CH = (NN + T - 1) / T;
    int t = threadIdx.x;
    int lane = t & 31, w = t >> 5;
    int base = t * CH;
    int sum = 0;
    for (int i = 0; i < CH; i++) { int idx = base + i; if (idx < NN) sum += g_deg[idx]; }
    int v = sum;
    #pragma unroll
    for (int o = 1; o < 32; o <<= 1) {
        int u = __shfl_up_sync(0xffffffffu, v, o);
        if (lane >= o) v += u;
    }
    if (lane == 31) wsum[w] = v;
    __syncthreads();
    if (w == 0) {
        int u = wsum[lane];
        #pragma unroll
        for (int o = 1; o < 32; o <<= 1) {
            int q = __shfl_up_sync(0xffffffffu, u, o);
            if (lane >= o) u += q;
        }
        wsum[lane] = u;
    }
    __syncthreads();
    int ex = v - sum + (w ? wsum[w - 1] : 0);
    for (int i = 0; i < CH; i++) {
        int idx = base + i;
        if (idx < NN) { g_off[idx] = ex; ex += g_deg[idx]; }
    }
    if (t == 0) g_off[NN] = ETOT;
}

__global__ void k_fill() {
    int e = blockIdx.x * blockDim.x + threadIdx.x;
    if (e >= ETOT) return;
    int d = g_dst[e];
    int pos = g_off[d] + atomicAdd(&g_cnt[d], 1);
    g_csr[pos] = g_src[e];
}

// ---------------- fold att vectors into W matrices ----------------
__global__ void k_prep(const float* __restrict__ W1s, const float* __restrict__ a1s,
                       const float* __restrict__ W1d, const float* __restrict__ a1d,
                       const float* __restrict__ W2s, const float* __restrict__ a2s,
                       const float* __restrict__ W2d, const float* __restrict__ a2d) {
    int t = threadIdx.x;   // 512
    {
        int f = t >> 2, h = t & 3;
        float ss = 0.f, sd = 0.f;
        #pragma unroll 8
        for (int c = 0; c < C1; c++) {
            ss += W1s[f * HC1 + h * C1 + c] * a1s[h * C1 + c];
            sd += W1d[f * HC1 + h * C1 + c] * a1d[h * C1 + c];
        }
        g_v1src[f * H1 + h] = ss;
        g_v1dst[f * H1 + h] = sd;
    }
    if (t < HC1) {
        float ss = 0.f, sd = 0.f;
        #pragma unroll 8
        for (int c = 0; c < C2; c++) {
            ss += W2s[t * C2 + c] * a2s[c];
            sd += W2d[t * C2 + c] * a2d[c];
        }
        g_v2src[t] = ss;
        g_v2dst[t] = sd;
    }
}

// ---------------- f32x2 packed GEMM: C[M,N] = A[M,K] @ B[K,N] ----------------
// Pairs along M: each FFMA2 computes two output rows at once.
template <int BM, int BN, int BK, int TM, int TN>
__global__ void sgemm2x(const float* __restrict__ A, const float* __restrict__ B,
                        float* __restrict__ C, int M, int K, int N) {
    static_assert(TM % 4 == 0, "TM multiple of 4");
    __shared__ float As[BK][BM];
    __shared__ float Bs[BK][BN];
    constexpr int THREADS = (BM / TM) * (BN / TN);
    const int t  = threadIdx.x;
    const int tx = t % (BN / TN);
    const int ty = t / (BN / TN);
    const int row0 = blockIdx.y * BM;
    const int col0 = blockIdx.x * BN;

    unsigned long long acc[TM / 2][TN];
    #pragma unroll
    for (int i = 0; i < TM / 2; i++)
        #pragma unroll
        for (int j = 0; j < TN; j++) acc[i][j] = 0ull;

    constexpr int A_F4 = BM * BK / 4;
    constexpr int B_F4 = BK * BN / 4;

    for (int k0 = 0; k0 < K; k0 += BK) {
        #pragma unroll
        for (int i = t; i < A_F4; i += THREADS) {
            int r = i / (BK / 4), c4 = i % (BK / 4);
            float4 v = make_float4(0.f, 0.f, 0.f, 0.f);
            int gr = row0 + r;
            if (gr < M) v = *(const float4*)&A[(size_t)gr * K + k0 + c4 * 4];
            As[c4 * 4 + 0][r] = v.x; As[c4 * 4 + 1][r] = v.y;
            As[c4 * 4 + 2][r] = v.z; As[c4 * 4 + 3][r] = v.w;
        }
        #pragma unroll
        for (int i = t; i < B_F4; i += THREADS) {
            int r = i / (BN / 4), c4 = i % (BN / 4);
            *(float4*)&Bs[r][c4 * 4] = *(const float4*)&B[(size_t)(k0 + r) * N + col0 + c4 * 4];
        }
        __syncthreads();
        #pragma unroll
        for (int k = 0; k < BK; k++) {
            // A pairs: a2[i] = M-rows (2i, 2i+1) of this thread's TM-row slice.
            // One ulonglong2 load covers 4 floats = pairs a2[i], a2[i+1]
            // starting at float offset 2*i within the slice.  (R6 bug: used 4*i.)
            unsigned long long a2[TM / 2];
            #pragma unroll
            for (int i = 0; i < TM / 2; i += 2) {
                ulonglong2 q = *(const ulonglong2*)&As[k][ty * TM + i * 2];
                a2[i] = q.x; a2[i + 1] = q.y;
            }
            float b[TN];
            #pragma unroll
            for (int j = 0; j < TN; j += 4) *(float4*)&b[j] = *(const float4*)&Bs[k][tx * TN + j];
            unsigned long long b2[TN];
            #pragma unroll
            for (int j = 0; j < TN; j++) b2[j] = pack2(b[j], b[j]);
            #pragma unroll
            for (int i = 0; i < TM / 2; i++)
                #pragma unroll
                for (int j = 0; j < TN; j++) ffma2(acc[i][j], a2[i], b2[j]);
        }
        __syncthreads();
    }
    #pragma unroll
    for (int i = 0; i < TM / 2; i++) {
        float lo[TN], hi[TN];
        #pragma unroll
        for (int j = 0; j < TN; j++) unpack2(acc[i][j], lo[j], hi[j]);
        int gr0 = row0 + ty * TM + 2 * i;
        if (gr0 < M) {
            #pragma unroll
            for (int j = 0; j < TN; j += 4)
                *(float4*)&C[(size_t)gr0 * N + col0 + tx * TN + j] =
                    make_float4(lo[j], lo[j + 1], lo[j + 2], lo[j + 3]);
        }
        if (gr0 + 1 < M) {
            #pragma unroll
            for (int j = 0; j < TN; j += 4)
                *(float4*)&C[(size_t)(gr0 + 1) * N + col0 + tx * TN + j] =
                    make_float4(hi[j], hi[j + 1], hi[j + 2], hi[j + 3]);
        }
    }
}

// ---------------- layer-1 per-node attention scalars from x only ----------------
__global__ void k_scores1(const float* __restrict__ x) {
    int warp = (blockIdx.x * blockDim.x + threadIdx.x) >> 5;
    int lane = threadIdx.x & 31;
    if (warp >= NN) return;

    float4 xv = *(const float4*)&x[(size_t)warp * FF + lane * 4];
    float s0 = 0, s1 = 0, s2 = 0, s3 = 0, d0 = 0, d1 = 0, d2 = 0, d3 = 0;
    #pragma unroll
    for (int j = 0; j < 4; j++) {
        int f = lane * 4 + j;
        float xf = (j == 0) ? xv.x : (j == 1) ? xv.y : (j == 2) ? xv.z : xv.w;
        float4 vs = *(const float4*)&g_v1src[f * H1];
        float4 vd = *(const float4*)&g_v1dst[f * H1];
        s0 += xf * vs.x; s1 += xf * vs.y; s2 += xf * vs.z; s3 += xf * vs.w;
        d0 += xf * vd.x; d1 += xf * vd.y; d2 += xf * vd.z; d3 += xf * vd.w;
    }
    #pragma unroll
    for (int o = 16; o > 0; o >>= 1) {
        s0 += __shfl_xor_sync(0xffffffffu, s0, o);
        s1 += __shfl_xor_sync(0xffffffffu, s1, o);
        s2 += __shfl_xor_sync(0xffffffffu, s2, o);
        s3 += __shfl_xor_sync(0xffffffffu, s3, o);
        d0 += __shfl_xor_sync(0xffffffffu, d0, o);
        d1 += __shfl_xor_sync(0xffffffffu, d1, o);
        d2 += __shfl_xor_sync(0xffffffffu, d2, o);
        d3 += __shfl_xor_sync(0xffffffffu, d3, o);
    }
    if (lane == 0) {
        *(float4*)&g_as1[warp * H1] = make_float4(s0, s1, s2, s3);
        *(float4*)&g_ad1[warp * H1] = make_float4(d0, d1, d2, d3);
    }
}

// ---------------- fused layer-1: softmax + aggregate + bias/relu + layer-2 scores ----------------
__global__ void k_fused1(const float* __restrict__ b1) {
    int node = (blockIdx.x * blockDim.x + threadIdx.x) >> 5;
    int lane = threadIdx.x & 31;
    if (node >= NN) return;
    int beg = g_off[node], end = g_off[node + 1];

    float4 ad = *(const float4*)&g_ad1[node * H1];

    float4 mx = make_float4(-FLT_MAX, -FLT_MAX, -FLT_MAX, -FLT_MAX);
    for (int i = beg + lane; i < end; i += 32) {
        int s = g_csr[i];
        float4 as = *(const float4*)&g_as1[s * H1];
        mx.x = fmaxf(mx.x, lrelu(as.x + ad.x));
        mx.y = fmaxf(mx.y, lrelu(as.y + ad.y));
        mx.z = fmaxf(mx.z, lrelu(as.z + ad.z));
        mx.w = fmaxf(mx.w, lrelu(as.w + ad.w));
    }
    #pragma unroll
    for (int o = 16; o > 0; o >>= 1) {
        mx.x = fmaxf(mx.x, __shfl_xor_sync(0xffffffffu, mx.x, o));
        mx.y = fmaxf(mx.y, __shfl_xor_sync(0xffffffffu, mx.y, o));
        mx.z = fmaxf(mx.z, __shfl_xor_sync(0xffffffffu, mx.z, o));
        mx.w = fmaxf(mx.w, __shfl_xor_sync(0xffffffffu, mx.w, o));
    }

    int head = lane >> 3;
    int col0 = lane * 8;
    float mh  = (head == 0) ? mx.x : (head == 1) ? mx.y : (head == 2) ? mx.z : mx.w;
    float adh = (head == 0) ? ad.x : (head == 1) ? ad.y : (head == 2) ? ad.z : ad.w;
    float den = 0.f;
    float acc[8];
    #pragma unroll
    for (int j = 0; j < 8; j++) acc[j] = 0.f;

    #pragma unroll 4
    for (int i = beg; i < end; i++) {
        int s = g_csr[i];
        float ex = __expf(lrelu(g_as1[s * H1 + head] + adh) - mh);
        den += ex;
        const float4* r = (const float4*)&g_xs1[(size_t)s * HC1 + col0];
        float4 v0 = r[0], v1 = r[1];
        acc[0] += ex * v0.x; acc[1] += ex * v0.y; acc[2] += ex * v0.z; acc[3] += ex * v0.w;
        acc[4] += ex * v1.x; acc[5] += ex * v1.y; acc[6] += ex * v1.z; acc[7] += ex * v1.w;
    }
    float inv = 1.f / den;
    float hrow[8];
    #pragma unroll
    for (int j = 0; j < 8; j++) hrow[j] = fmaxf(acc[j] * inv + b1[col0 + j], 0.f);

    float* hp = &g_h[(size_t)node * HC1 + col0];
    *(float4*)&hp[0] = make_float4(hrow[0], hrow[1], hrow[2], hrow[3]);
    *(float4*)&hp[4] = make_float4(hrow[4], hrow[5], hrow[6], hrow[7]);

    float ps = 0.f, pd = 0.f;
    #pragma unroll
    for (int j = 0; j < 8; j++) {
        ps += hrow[j] * g_v2src[col0 + j];
        pd += hrow[j] * g_v2dst[col0 + j];
    }
    #pragma unroll
    for (int o = 16; o > 0; o >>= 1) {
        ps += __shfl_xor_sync(0xffffffffu, ps, o);
        pd += __shfl_xor_sync(0xffffffffu, pd, o);
    }
    if (lane == 0) { g_as2[node] = ps; g_ad2[node] = pd; }
}

// ---------------- fused layer-2: softmax + aggregate + bias ----------------
__global__ void k_fused2(float* __restrict__ out, const float* __restrict__ b2) {
    int node = (blockIdx.x * blockDim.x + threadIdx.x) >> 5;
    int lane = threadIdx.x & 31;
    if (node >= NN) return;
    int beg = g_off[node], end = g_off[node + 1];
    float adn = g_ad2[node];

    float mx = -FLT_MAX;
    for (int i = beg + lane; i < end; i += 32)
        mx = fmaxf(mx, lrelu(g_as2[g_csr[i]] + adn));
    #pragma unroll
    for (int o = 16; o > 0; o >>= 1)
        mx = fmaxf(mx, __shfl_xor_sync(0xffffffffu, mx, o));

    int col = lane * 2;
    float den = 0.f, a0 = 0.f, a1 = 0.f;
    #pragma unroll 4
    for (int i = beg; i < end; i++) {
        int s = g_csr[i];
        float ex = __expf(lrelu(g_as2[s] + adn) - mx);
        den += ex;
        float2 v = *(const float2*)&g_xs2[(size_t)s * C2 + col];
        a0 += ex * v.x; a1 += ex * v.y;
    }
    float inv = 1.f / den;
    *(float2*)&out[(size_t)node * C2 + col] =
        make_float2(a0 * inv + b2[col], a1 * inv + b2[col + 1]);
}

// ---------------- launcher ----------------
extern "C" void kernel_launch(void* const* d_in, const int* in_sizes, int n_in,
                              void* d_out, int out_size) {
    const float* x    = (const float*)d_in[0];
    const void*  ei   = d_in[1];
    const float* W1s  = (const float*)d_in[2];
    const float* W1d  = (const float*)d_in[3];
    const float* a1s  = (const float*)d_in[4];
    const float* a1d  = (const float*)d_in[5];
    const float* b1   = (const float*)d_in[6];
    const float* W2s  = (const float*)d_in[7];
    const float* W2d  = (const float*)d_in[8];
    const float* a2s  = (const float*)d_in[9];
    const float* a2d  = (const float*)d_in[10];
    const float* b2   = (const float*)d_in[11];
    float* out = (float*)d_out;

    cudaStream_t st = 0;

    // lazily-created side stream + fork/join events (host-side objects only)
    static cudaStream_t s_side = nullptr;
    static cudaEvent_t  ev_fork = nullptr, ev_join = nullptr;
    if (!s_side) {
        cudaStreamCreateWithFlags(&s_side, cudaStreamNonBlocking);
        cudaEventCreateWithFlags(&ev_fork, cudaEventDisableTiming);
        cudaEventCreateWithFlags(&ev_join, cudaEventDisableTiming);
    }

    void *p_deg, *p_cnt;
    cudaGetSymbolAddress(&p_deg, g_deg);
    cudaGetSymbolAddress(&p_cnt, g_cnt);

    // ---- fork: CSR build + scores on side stream, GEMM1 on main ----
    cudaEventRecord(ev_fork, st);
    cudaStreamWaitEvent(s_side, ev_fork, 0);

    cudaMemsetAsync(p_deg, 0, NN * sizeof(int), s_side);
    cudaMemsetAsync(p_cnt, 0, NN * sizeof(int), s_side);
    int eb = (ETOT + 255) / 256;
    k_detect<<<1, 32, 0, s_side>>>((const int*)ei);
    k_decode<<<eb, 256, 0, s_side>>>(ei);
    k_scan<<<1, 1024, 0, s_side>>>();
    k_fill<<<eb, 256, 0, s_side>>>();
    k_prep<<<1, 512, 0, s_side>>>(W1s, a1s, W1d, a1d, W2s, a2s, W2d, a2d);
    k_scores1<<<(NN * 32 + 255) / 256, 256, 0, s_side>>>(x);
    cudaEventRecord(ev_join, s_side);

    // xs1 = x @ W1_src   [50000,128] x [128,256]
    {
        float* xs1; cudaGetSymbolAddress((void**)&xs1, g_xs1);
        dim3 grid(HC1 / 64, (NN + 127) / 128);
        sgemm2x<128, 64, 16, 8, 4><<<grid, 256, 0, st>>>(x, W1s, xs1, NN, FF, HC1);
    }

    cudaStreamWaitEvent(st, ev_join, 0);   // join before fused1

    int nb = (NN * 32 + 255) / 256;
    k_fused1<<<nb, 256, 0, st>>>(b1);

    // xs2 = h @ W2_src   [50000,256] x [256,64]
    {
        float *h, *xs2;
        cudaGetSymbolAddress((void**)&h, g_h);
        cudaGetSymbolAddress((void**)&xs2, g_xs2);
        dim3 grid(C2 / 64, (NN + 127) / 128);
        sgemm2x<128, 64, 16, 8, 4><<<grid, 256, 0, st>>>(h, W2s, xs2, NN, HC1, C2);
    }

    k_fused2<<<nb, 256, 0, st>>>(out, b2);
}

// round 9
// speedup vs baseline: 1.3544x; 1.2104x over previous
#include <cuda_runtime.h>
#include <cuda_bf16.h>
#include <cstdint>
#include <cfloat>

#define NN   50000
#define FF   128
#define H1   4
#define C1   64
#define HC1  256     // H1*C1
#define C2   64
#define EE   400000
#define ETOT (EE + NN)

// ---------------- scratch (static __device__, no allocs) ----------------
__device__ __align__(16) float g_xs1[(size_t)NN * HC1];   // x @ W1_src
__device__ __align__(16) float g_h  [(size_t)NN * HC1];   // hidden (post bias+relu)
__device__ __align__(16) float g_xs2[(size_t)NN * C2];    // h @ W2_src
__device__ __align__(16) float g_as1[NN * H1];
__device__ __align__(16) float g_ad1[NN * H1];
__device__ __align__(16) float g_as2[NN];
__device__ __align__(16) float g_ad2[NN];
__device__ __align__(16) float g_v1src[FF * H1];
__device__ __align__(16) float g_v1dst[FF * H1];
__device__ __align__(16) float g_v2src[HC1];
__device__ __align__(16) float g_v2dst[HC1];
__device__ __align__(16) int   g_src[ETOT];
__device__ __align__(16) int   g_dst[ETOT];
__device__ __align__(16) int   g_deg[NN];
__device__ __align__(16) int   g_cnt[NN];
__device__ __align__(16) int   g_off[NN + 1];
__device__ __align__(16) int   g_csr[ETOT];
__device__ int g_is32;
// transposed bf16 hi/lo weights for MMA GEMMs: [N, K] row-major
__device__ __align__(16) __nv_bfloat16 g_w1hi[HC1 * FF];   // [256,128]
__device__ __align__(16) __nv_bfloat16 g_w1lo[HC1 * FF];
__device__ __align__(16) __nv_bfloat16 g_w2hi[C2 * HC1];   // [64,256]
__device__ __align__(16) __nv_bfloat16 g_w2lo[C2 * HC1];

// ---------------- helpers ----------------
__device__ __forceinline__ float lrelu(float v) { return v > 0.f ? v : 0.2f * v; }

__device__ __forceinline__ uint32_t su32(const void* p) {
    return (uint32_t)__cvta_generic_to_shared(p);
}
__device__ __forceinline__ uint32_t pk(__nv_bfloat16 a, __nv_bfloat16 b) {
    __nv_bfloat162 t(a, b);
    return *(uint32_t*)&t;
}
__device__ __forceinline__ void ldsm4(uint32_t& r0, uint32_t& r1, uint32_t& r2, uint32_t& r3,
                                      uint32_t addr) {
    asm volatile("ldmatrix.sync.aligned.m8n8.x4.shared.b16 {%0,%1,%2,%3}, [%4];"
                 : "=r"(r0), "=r"(r1), "=r"(r2), "=r"(r3) : "r"(addr));
}
__device__ __forceinline__ void mma16816(float* c, const uint32_t* a, uint32_t b0, uint32_t b1) {
    asm volatile("mma.sync.aligned.m16n8k16.row.col.f32.bf16.bf16.f32 "
                 "{%0,%1,%2,%3}, {%4,%5,%6,%7}, {%8,%9}, {%0,%1,%2,%3};"
                 : "+f"(c[0]), "+f"(c[1]), "+f"(c[2]), "+f"(c[3])
                 : "r"(a[0]), "r"(a[1]), "r"(a[2]), "r"(a[3]), "r"(b0), "r"(b1));
}

// ---------------- edge dtype detection ----------------
__global__ void k_detect(const int* __restrict__ ei32) {
    int lane = threadIdx.x;
    int nz = 0;
    #pragma unroll
    for (int j = 0; j < 4; j++) nz |= ei32[2 * (lane * 4 + j) + 1];
    unsigned anynz = __ballot_sync(0xffffffffu, nz != 0);
    if (lane == 0) g_is32 = (anynz != 0u) ? 1 : 0;
}

__global__ void k_decode(const void* __restrict__ ei) {
    int e = blockIdx.x * blockDim.x + threadIdx.x;
    if (e >= ETOT) return;
    int s, d;
    if (e < EE) {
        if (g_is32) {
            const int* p = (const int*)ei;
            s = p[e]; d = p[EE + e];
        } else {
            const long long* p = (const long long*)ei;
            s = (int)p[e]; d = (int)p[EE + e];
        }
    } else {
        s = e - EE; d = s;
    }
    g_src[e] = s; g_dst[e] = d;
    atomicAdd(&g_deg[d], 1);
}

// single-block exclusive scan of g_deg -> g_off
__global__ void k_scan() {
    __shared__ int wsum[32];
    const int T = 1024;
    const int CH = (NN + T - 1) / T;
    int t = threadIdx.x;
    int lane = t & 31, w = t >> 5;
    int base = t * CH;
    int sum = 0;
    for (int i = 0; i < CH; i++) { int idx = base + i; if (idx < NN) sum += g_deg[idx]; }
    int v = sum;
    #pragma unroll
    for (int o = 1; o < 32; o <<= 1) {
        int u = __shfl_up_sync(0xffffffffu, v, o);
        if (lane >= o) v += u;
    }
    if (lane == 31) wsum[w] = v;
    __syncthreads();
    if (w == 0) {
        int u = wsum[lane];
        #pragma unroll
        for (int o = 1; o < 32; o <<= 1) {
            int q = __shfl_up_sync(0xffffffffu, u, o);
            if (lane >= o) u += q;
        }
        wsum[lane] = u;
    }
    __syncthreads();
    int ex = v - sum + (w ? wsum[w - 1] : 0);
    for (int i = 0; i < CH; i++) {
        int idx = base + i;
        if (idx < NN) { g_off[idx] = ex; ex += g_deg[idx]; }
    }
    if (t == 0) g_off[NN] = ETOT;
}

__global__ void k_fill() {
    int e = blockIdx.x * blockDim.x + threadIdx.x;
    if (e >= ETOT) return;
    int d = g_dst[e];
    int pos = g_off[d] + atomicAdd(&g_cnt[d], 1);
    g_csr[pos] = g_src[e];
}

// ---------------- fold att vectors into W matrices ----------------
__global__ void k_prep(const float* __restrict__ W1s, const float* __restrict__ a1s,
                       const float* __restrict__ W1d, const float* __restrict__ a1d,
                       const float* __restrict__ W2s, const float* __restrict__ a2s,
                       const float* __restrict__ W2d, const float* __restrict__ a2d) {
    int t = threadIdx.x;   // 512
    {
        int f = t >> 2, h = t & 3;
        float ss = 0.f, sd = 0.f;
        #pragma unroll 8
        for (int c = 0; c < C1; c++) {
            ss += W1s[f * HC1 + h * C1 + c] * a1s[h * C1 + c];
            sd += W1d[f * HC1 + h * C1 + c] * a1d[h * C1 + c];
        }
        g_v1src[f * H1 + h] = ss;
        g_v1dst[f * H1 + h] = sd;
    }
    if (t < HC1) {
        float ss = 0.f, sd = 0.f;
        #pragma unroll 8
        for (int c = 0; c < C2; c++) {
            ss += W2s[t * C2 + c] * a2s[c];
            sd += W2d[t * C2 + c] * a2d[c];
        }
        g_v2src[t] = ss;
        g_v2dst[t] = sd;
    }
}

// ---------------- transpose + bf16 hi/lo split of the GEMM weights ----------------
__global__ void k_convW(const float* __restrict__ W1s, const float* __restrict__ W2s) {
    int i = blockIdx.x * blockDim.x + threadIdx.x;
    if (i < HC1 * FF) {                          // W1t [256,128]
        int n = i >> 7, k = i & 127;
        float v = W1s[(size_t)k * HC1 + n];
        __nv_bfloat16 h = __float2bfloat16(v);
        g_w1hi[i] = h;
        g_w1lo[i] = __float2bfloat16(v - __bfloat162float(h));
    }
    if (i < C2 * HC1) {                          // W2t [64,256]
        int n = i >> 8, k = i & 255;
        float v = W2s[(size_t)k * C2 + n];
        __nv_bfloat16 h = __float2bfloat16(v);
        g_w2hi[i] = h;
        g_w2lo[i] = __float2bfloat16(v - __bfloat162float(h));
    }
}

// ---------------- bf16-split HMMA GEMM: C[M,N_TOTAL] = A[M,K] @ Bt[N,K]^T ----------
// CTA tile 128x64, 8 warps (4M x 2N), warp tile 32x32. K chunked at 128.
// A fp32 -> bf16 hi/lo in-kernel; Bt pre-split. acc fp32 over 3 combos.
template <int K_TOTAL, int N_TOTAL>
__global__ __launch_bounds__(256)
void k_hmma(const float* __restrict__ A, const __nv_bfloat16* __restrict__ Bhi,
            const __nv_bfloat16* __restrict__ Blo, float* __restrict__ C, int M) {
    constexpr int KC = 128;
    constexpr int NCH = K_TOTAL / KC;
    constexpr int RS = 272;                        // smem row stride bytes (136 bf16)
    constexpr uint32_t A_HI = 0;
    constexpr uint32_t A_LO = 128 * RS;
    constexpr uint32_t B_HI = 256 * RS;
    constexpr uint32_t B_LO = 320 * RS;            // total 384*RS = 104448 B

    extern __shared__ char sm[];
    const uint32_t base = su32(sm);

    const int tid = threadIdx.x, l = tid & 31, w = tid >> 5;
    const int wm = w & 3, wn = w >> 2;             // 4 x 2 warp grid
    const int row0 = blockIdx.y * 128;
    const int col0 = blockIdx.x * 64;

    // ldmatrix per-thread byte offsets (within a buffer)
    const uint32_t aOff = (uint32_t)((wm * 32 + (l & 15)) * RS + (l >> 4) * 16);
    const uint32_t bOff = (uint32_t)((wn * 32 + ((l >> 4) & 1) * 8 + (l & 7)) * RS
                                     + ((l >> 3) & 1) * 16);

    float acc[2][4][4];
    #pragma unroll
    for (int mt = 0; mt < 2; mt++)
        #pragma unroll
        for (int nt = 0; nt < 4; nt++)
            #pragma unroll
            for (int q = 0; q < 4; q++) acc[mt][nt][q] = 0.f;

    for (int ch = 0; ch < NCH; ch++) {
        // ---- load A tile [128 x 128 f32], split to bf16 hi/lo ----
        #pragma unroll
        for (int j = 0; j < 16; j++) {
            int idx = j * 256 + tid;               // float4 index in [128 x 32]
            int r = idx >> 5, c4 = (idx & 31) * 4;
            int gr = row0 + r;
            float4 v = make_float4(0.f, 0.f, 0.f, 0.f);
            if (gr < M) v = *(const float4*)&A[(size_t)gr * K_TOTAL + ch * KC + c4];
            __nv_bfloat16 h0 = __float2bfloat16(v.x), h1 = __float2bfloat16(v.y),
                          h2 = __float2bfloat16(v.z), h3 = __float2bfloat16(v.w);
            uint32_t o = r * RS + c4 * 2;
            *(uint2*)(sm + A_HI + o) = make_uint2(pk(h0, h1), pk(h2, h3));
            *(uint2*)(sm + A_LO + o) = make_uint2(
                pk(__float2bfloat16(v.x - __bfloat162float(h0)),
                   __float2bfloat16(v.y - __bfloat162float(h1))),
                pk(__float2bfloat16(v.z - __bfloat162float(h2)),
                   __float2bfloat16(v.w - __bfloat162float(h3))));
        }
        // ---- load B tile [64 x 128 bf16] hi/lo ----
        #pragma unroll
        for (int j = 0; j < 8; j++) {
            int idx = j * 256 + tid;               // 4-bf16 chunk in [64 x 32]
            int r = idx >> 5, c4 = (idx & 31) * 4;
            size_t go = (size_t)(col0 + r) * K_TOTAL + ch * KC + c4;
            uint32_t o = r * RS + c4 * 2;
            *(uint2*)(sm + B_HI + o) = *(const uint2*)&Bhi[go];
            *(uint2*)(sm + B_LO + o) = *(const uint2*)&Blo[go];
        }
        __syncthreads();

        #pragma unroll
        for (int ks = 0; ks < 8; ks++) {
            uint32_t ah[2][4], al[2][4], bh[2][4], bl[2][4];
            #pragma unroll
            for (int mt = 0; mt < 2; mt++) {
                uint32_t ao = aOff + mt * 16 * RS + ks * 32;
                ldsm4(ah[mt][0], ah[mt][1], ah[mt][2], ah[mt][3], base + A_HI + ao);
                ldsm4(al[mt][0], al[mt][1], al[mt][2], al[mt][3], base + A_LO + ao);
            }
            #pragma unroll
            for (int np = 0; np < 2; np++) {
                uint32_t bo = bOff + np * 16 * RS + ks * 32;
                ldsm4(bh[np][0], bh[np][1], bh[np][2], bh[np][3], base + B_HI + bo);
                ldsm4(bl[np][0], bl[np][1], bl[np][2], bl[np][3], base + B_LO + bo);
            }
            #pragma unroll
            for (int mt = 0; mt < 2; mt++)
                #pragma unroll
                for (int nt = 0; nt < 4; nt++) {
                    uint32_t bh0 = bh[nt >> 1][(nt & 1) * 2], bh1 = bh[nt >> 1][(nt & 1) * 2 + 1];
                    uint32_t bl0 = bl[nt >> 1][(nt & 1) * 2], bl1 = bl[nt >> 1][(nt & 1) * 2 + 1];
                    mma16816(acc[mt][nt], ah[mt], bh0, bh1);   // hi*hi
                    mma16816(acc[mt][nt], al[mt], bh0, bh1);   // lo*hi
                    mma16816(acc[mt][nt], ah[mt], bl0, bl1);   // hi*lo
                }
        }
        __syncthreads();
    }

    // ---- writeback ----
    #pragma unroll
    for (int mt = 0; mt < 2; mt++)
        #pragma unroll
        for (int nt = 0; nt < 4; nt++) {
            int m0 = row0 + wm * 32 + mt * 16 + (l >> 2);
            int n  = col0 + wn * 32 + nt * 8 + (l & 3) * 2;
            if (m0 < M)
                *(float2*)&C[(size_t)m0 * N_TOTAL + n] =
                    make_float2(acc[mt][nt][0], acc[mt][nt][1]);
            if (m0 + 8 < M)
                *(float2*)&C[(size_t)(m0 + 8) * N_TOTAL + n] =
                    make_float2(acc[mt][nt][2], acc[mt][nt][3]);
        }
}

// ---------------- layer-1 per-node attention scalars from x only ----------------
__global__ void k_scores1(const float* __restrict__ x) {
    int warp = (blockIdx.x * blockDim.x + threadIdx.x) >> 5;
    int lane = threadIdx.x & 31;
    if (warp >= NN) return;

    float4 xv = *(const float4*)&x[(size_t)warp * FF + lane * 4];
    float s0 = 0, s1 = 0, s2 = 0, s3 = 0, d0 = 0, d1 = 0, d2 = 0, d3 = 0;
    #pragma unroll
    for (int j = 0; j < 4; j++) {
        int f = lane * 4 + j;
        float xf = (j == 0) ? xv.x : (j == 1) ? xv.y : (j == 2) ? xv.z : xv.w;
        float4 vs = *(const float4*)&g_v1src[f * H1];
        float4 vd = *(const float4*)&g_v1dst[f * H1];
        s0 += xf * vs.x; s1 += xf * vs.y; s2 += xf * vs.z; s3 += xf * vs.w;
        d0 += xf * vd.x; d1 += xf * vd.y; d2 += xf * vd.z; d3 += xf * vd.w;
    }
    #pragma unroll
    for (int o = 16; o > 0; o >>= 1) {
        s0 += __shfl_xor_sync(0xffffffffu, s0, o);
        s1 += __shfl_xor_sync(0xffffffffu, s1, o);
        s2 += __shfl_xor_sync(0xffffffffu, s2, o);
        s3 += __shfl_xor_sync(0xffffffffu, s3, o);
        d0 += __shfl_xor_sync(0xffffffffu, d0, o);
        d1 += __shfl_xor_sync(0xffffffffu, d1, o);
        d2 += __shfl_xor_sync(0xffffffffu, d2, o);
        d3 += __shfl_xor_sync(0xffffffffu, d3, o);
    }
    if (lane == 0) {
        *(float4*)&g_as1[warp * H1] = make_float4(s0, s1, s2, s3);
        *(float4*)&g_ad1[warp * H1] = make_float4(d0, d1, d2, d3);
    }
}

// ---------------- fused layer-1: softmax + aggregate + bias/relu + layer-2 scores ----------------
__global__ void k_fused1(const float* __restrict__ b1) {
    int node = (blockIdx.x * blockDim.x + threadIdx.x) >> 5;
    int lane = threadIdx.x & 31;
    if (node >= NN) return;
    int beg = g_off[node], end = g_off[node + 1];

    float4 ad = *(const float4*)&g_ad1[node * H1];

    float4 mx = make_float4(-FLT_MAX, -FLT_MAX, -FLT_MAX, -FLT_MAX);
    for (int i = beg + lane; i < end; i += 32) {
        int s = g_csr[i];
        float4 as = *(const float4*)&g_as1[s * H1];
        mx.x = fmaxf(mx.x, lrelu(as.x + ad.x));
        mx.y = fmaxf(mx.y, lrelu(as.y + ad.y));
        mx.z = fmaxf(mx.z, lrelu(as.z + ad.z));
        mx.w = fmaxf(mx.w, lrelu(as.w + ad.w));
    }
    #pragma unroll
    for (int o = 16; o > 0; o >>= 1) {
        mx.x = fmaxf(mx.x, __shfl_xor_sync(0xffffffffu, mx.x, o));
        mx.y = fmaxf(mx.y, __shfl_xor_sync(0xffffffffu, mx.y, o));
        mx.z = fmaxf(mx.z, __shfl_xor_sync(0xffffffffu, mx.z, o));
        mx.w = fmaxf(mx.w, __shfl_xor_sync(0xffffffffu, mx.w, o));
    }

    int head = lane >> 3;
    int col0 = lane * 8;
    float mh  = (head == 0) ? mx.x : (head == 1) ? mx.y : (head == 2) ? mx.z : mx.w;
    float adh = (head == 0) ? ad.x : (head == 1) ? ad.y : (head == 2) ? ad.z : ad.w;
    float den = 0.f;
    float acc[8];
    #pragma unroll
    for (int j = 0; j < 8; j++) acc[j] = 0.f;

    #pragma unroll 4
    for (int i = beg; i < end; i++) {
        int s = g_csr[i];
        float ex = __expf(lrelu(g_as1[s * H1 + head] + adh) - mh);
        den += ex;
        const float4* r = (const float4*)&g_xs1[(size_t)s * HC1 + col0];
        float4 v0 = r[0], v1 = r[1];
        acc[0] += ex * v0.x; acc[1] += ex * v0.y; acc[2] += ex * v0.z; acc[3] += ex * v0.w;
        acc[4] += ex * v1.x; acc[5] += ex * v1.y; acc[6] += ex * v1.z; acc[7] += ex * v1.w;
    }
    float inv = 1.f / den;
    float hrow[8];
    #pragma unroll
    for (int j = 0; j < 8; j++) hrow[j] = fmaxf(acc[j] * inv + b1[col0 + j], 0.f);

    float* hp = &g_h[(size_t)node * HC1 + col0];
    *(float4*)&hp[0] = make_float4(hrow[0], hrow[1], hrow[2], hrow[3]);
    *(float4*)&hp[4] = make_float4(hrow[4], hrow[5], hrow[6], hrow[7]);

    float ps = 0.f, pd = 0.f;
    #pragma unroll
    for (int j = 0; j < 8; j++) {
        ps += hrow[j] * g_v2src[col0 + j];
        pd += hrow[j] * g_v2dst[col0 + j];
    }
    #pragma unroll
    for (int o = 16; o > 0; o >>= 1) {
        ps += __shfl_xor_sync(0xffffffffu, ps, o);
        pd += __shfl_xor_sync(0xffffffffu, pd, o);
    }
    if (lane == 0) { g_as2[node] = ps; g_ad2[node] = pd; }
}

// ---------------- fused layer-2: softmax + aggregate + bias ----------------
__global__ void k_fused2(float* __restrict__ out, const float* __restrict__ b2) {
    int node = (blockIdx.x * blockDim.x + threadIdx.x) >> 5;
    int lane = threadIdx.x & 31;
    if (node >= NN) return;
    int beg = g_off[node], end = g_off[node + 1];
    float adn = g_ad2[node];

    float mx = -FLT_MAX;
    for (int i = beg + lane; i < end; i += 32)
        mx = fmaxf(mx, lrelu(g_as2[g_csr[i]] + adn));
    #pragma unroll
    for (int o = 16; o > 0; o >>= 1)
        mx = fmaxf(mx, __shfl_xor_sync(0xffffffffu, mx, o));

    int col = lane * 2;
    float den = 0.f, a0 = 0.f, a1 = 0.f;
    #pragma unroll 4
    for (int i = beg; i < end; i++) {
        int s = g_csr[i];
        float ex = __expf(lrelu(g_as2[s] + adn) - mx);
        den += ex;
        float2 v = *(const float2*)&g_xs2[(size_t)s * C2 + col];
        a0 += ex * v.x; a1 += ex * v.y;
    }
    float inv = 1.f / den;
    *(float2*)&out[(size_t)node * C2 + col] =
        make_float2(a0 * inv + b2[col], a1 * inv + b2[col + 1]);
}

// ---------------- launcher ----------------
extern "C" void kernel_launch(void* const* d_in, const int* in_sizes, int n_in,
                              void* d_out, int out_size) {
    const float* x    = (const float*)d_in[0];
    const void*  ei   = d_in[1];
    const float* W1s  = (const float*)d_in[2];
    const float* W1d  = (const float*)d_in[3];
    const float* a1s  = (const float*)d_in[4];
    const float* a1d  = (const float*)d_in[5];
    const float* b1   = (const float*)d_in[6];
    const float* W2s  = (const float*)d_in[7];
    const float* W2d  = (const float*)d_in[8];
    const float* a2s  = (const float*)d_in[9];
    const float* a2d  = (const float*)d_in[10];
    const float* b2   = (const float*)d_in[11];
    float* out = (float*)d_out;

    cudaStream_t st = 0;

    constexpr int SMEM_MMA = 384 * 272;    // 104448 B
    constexpr int NT = (NN + 127) / 128;   // 391 M-tiles

    static cudaStream_t s_side = nullptr;
    static cudaEvent_t  ev_fork = nullptr, ev_join = nullptr;
    if (!s_side) {
        cudaStreamCreateWithFlags(&s_side, cudaStreamNonBlocking);
        cudaEventCreateWithFlags(&ev_fork, cudaEventDisableTiming);
        cudaEventCreateWithFlags(&ev_join, cudaEventDisableTiming);
        cudaFuncSetAttribute(k_hmma<128, 256>, cudaFuncAttributeMaxDynamicSharedMemorySize, SMEM_MMA);
        cudaFuncSetAttribute(k_hmma<256, 64>,  cudaFuncAttributeMaxDynamicSharedMemorySize, SMEM_MMA);
    }

    void *p_deg, *p_cnt, *p_xs1, *p_h, *p_xs2, *p_w1h, *p_w1l, *p_w2h, *p_w2l;
    cudaGetSymbolAddress(&p_deg, g_deg);
    cudaGetSymbolAddress(&p_cnt, g_cnt);
    cudaGetSymbolAddress(&p_xs1, g_xs1);
    cudaGetSymbolAddress(&p_h,   g_h);
    cudaGetSymbolAddress(&p_xs2, g_xs2);
    cudaGetSymbolAddress(&p_w1h, g_w1hi);
    cudaGetSymbolAddress(&p_w1l, g_w1lo);
    cudaGetSymbolAddress(&p_w2h, g_w2hi);
    cudaGetSymbolAddress(&p_w2l, g_w2lo);

    // ---- fork: CSR build + scores on side stream; weight conv + GEMM1 on main ----
    cudaEventRecord(ev_fork, st);
    cudaStreamWaitEvent(s_side, ev_fork, 0);

    cudaMemsetAsync(p_deg, 0, NN * sizeof(int), s_side);
    cudaMemsetAsync(p_cnt, 0, NN * sizeof(int), s_side);
    int eb = (ETOT + 255) / 256;
    k_detect<<<1, 32, 0, s_side>>>((const int*)ei);
    k_decode<<<eb, 256, 0, s_side>>>(ei);
    k_scan<<<1, 1024, 0, s_side>>>();
    k_fill<<<eb, 256, 0, s_side>>>();
    k_prep<<<1, 512, 0, s_side>>>(W1s, a1s, W1d, a1d, W2s, a2s, W2d, a2d);
    k_scores1<<<(NN * 32 + 255) / 256, 256, 0, s_side>>>(x);
    cudaEventRecord(ev_join, s_side);

    k_convW<<<(HC1 * FF + 255) / 256, 256, 0, st>>>(W1s, W2s);

    // xs1 = x @ W1_src   [50000,128] x [128,256] via bf16-split HMMA
    {
        dim3 grid(HC1 / 64, NT);
        k_hmma<128, 256><<<grid, 256, SMEM_MMA, st>>>(
            x, (const __nv_bfloat16*)p_w1h, (const __nv_bfloat16*)p_w1l, (float*)p_xs1, NN);
    }

    cudaStreamWaitEvent(st, ev_join, 0);   // join before fused1

    int nb = (NN * 32 + 255) / 256;
    k_fused1<<<nb, 256, 0, st>>>(b1);

    // xs2 = h @ W2_src   [50000,256] x [256,64]
    {
        dim3 grid(C2 / 64, NT);
        k_hmma<256, 64><<<grid, 256, SMEM_MMA, st>>>(
            (const float*)p_h, (const __nv_bfloat16*)p_w2h, (const __nv_bfloat16*)p_w2l,
            (float*)p_xs2, NN);
    }

    k_fused2<<<nb, 256, 0, st>>>(out, b2);
}